// round 7
// baseline (speedup 1.0000x reference)
#include <cuda_runtime.h>

// HMM forward: alpha_{t+1} = (alpha_t @ A) * Bo[t],  answer = sum(alpha_{T-1})
//
// R7 = R5 (exact math: 128 CTAs, 8 warps, warp-per-column-group, k-ascending
// FMA2 chains, xor-butterfly reduction — measured rel_err 9.477166e-4)
// + two-level fan-in grid barrier. R6 calibrated the single-counter barrier
// at ~2us/step (128 same-address atomics serialize ~27cyc each in the LTS
// atomic ALU). Fan-in: 16 leaf counters (distinct 128B lines, 8 CTAs each,
// parallel) -> root counter -> sense flip. Arrival ~3456 -> ~650 cyc.

#define N_STATES 4096
#define SEQ_T    1024
#define N_OBS    128
#define NCTA     128
#define NTHR     256
#define COLS_PER_CTA 32

#define KR 44
#define KS 51
#define KT 33                       // 44+51+33 = 128
#define R_ROWS (KR * 32)            // 1408
#define S_ROWS (KS * 32)            // 1632
#define T3_OFF (R_ROWS + S_ROWS)    // 3040
#define T3_ROWS (KT * 32)           // 1056
#define S_PITCH (S_ROWS + 1)

#define NLEAF 16
#define LEAF_SZ (NCTA / NLEAF)      // 8

// dynamic smem: sA[8][S_PITCH] float4  +  s_alpha[4096] float
#define SMEM_BYTES (8 * S_PITCH * 16 + N_STATES * 4)

__device__ float    g_Bo[SEQ_T * N_STATES];
__device__ float4   g_A3T[1024 * T3_ROWS];     // [cg_global][row-T3_OFF]
__device__ float    g_alpha[2][N_STATES];
__device__ unsigned g_leaf[NLEAF * 32];        // one counter per 128B line
__device__ unsigned g_root;
__device__ unsigned g_sense;                   // even #flips/launch -> restored

// ---------------------------------------------------------------------------
__global__ void gather_Bo_kernel(const float* __restrict__ B,
                                 const int*   __restrict__ obs_raw) {
    int any = 0;
    for (int k = 1 + 2 * (int)threadIdx.x; k < 1024; k += 2 * (int)blockDim.x)
        any |= obs_raw[k];
    int is32 = __syncthreads_or(any);

    int t = blockIdx.x;
    int o = is32 ? obs_raw[t] : obs_raw[2 * t];

    for (int j = threadIdx.x; j < N_STATES; j += blockDim.x)
        g_Bo[t * N_STATES + j] = B[j * N_OBS + o];
}

// ---------------------------------------------------------------------------
__global__ void transpose_A3_kernel(const float* __restrict__ A) {
    __shared__ float4 tile[32][33];
    const float4* A4 = reinterpret_cast<const float4*>(A);
    int r0 = blockIdx.x * 32;
    int c0 = blockIdx.y * 32;
    int tx = threadIdx.x & 31, ty = threadIdx.x >> 5;
    #pragma unroll
    for (int p = 0; p < 4; ++p) {
        int r = r0 + ty + 8 * p;
        tile[ty + 8 * p][tx] = A4[(size_t)(T3_OFF + r) * 1024 + (c0 + tx)];
    }
    __syncthreads();
    #pragma unroll
    for (int p = 0; p < 4; ++p) {
        int c = c0 + ty + 8 * p;
        g_A3T[(size_t)c * T3_ROWS + (r0 + tx)] = tile[tx][ty + 8 * p];
    }
}

// ---------------------------------------------------------------------------
// Two-level fan-in grid barrier (sense-reversing).
__device__ __forceinline__ void grid_barrier(unsigned& local_sense, int cta) {
    __syncthreads();
    if (threadIdx.x == 0) {
        unsigned s = local_sense ^ 1u;
        local_sense = s;
        __threadfence();                                   // release
        int l = (cta & (NLEAF - 1)) * 32;
        if (atomicAdd(&g_leaf[l], 1u) == LEAF_SZ - 1u) {
            g_leaf[l] = 0u;
            __threadfence();
            if (atomicAdd(&g_root, 1u) == NLEAF - 1u) {
                g_root = 0u;
                __threadfence();
                atomicExch(&g_sense, s);
            } else {
                while (*(volatile unsigned*)&g_sense != s) { }
            }
        } else {
            while (*(volatile unsigned*)&g_sense != s) { }
        }
        __threadfence();                                   // acquire
    }
    __syncthreads();
}

// packed f32x2 fma: component-wise IEEE fp32 fma (bit-identical to scalar)
__device__ __forceinline__ void fma2(unsigned long long& d,
                                     unsigned long long v,
                                     unsigned long long a) {
    asm("fma.rn.f32x2 %0, %1, %2, %0;" : "+l"(d) : "l"(v), "l"(a));
}
__device__ __forceinline__ unsigned long long pack2(float a) {
    unsigned long long r;
    asm("mov.b64 %0, {%1, %2};" : "=l"(r) : "f"(a), "f"(a));
    return r;
}

// ---------------------------------------------------------------------------
__global__ void __launch_bounds__(NTHR, 1)
hmm_forward_kernel(const float* __restrict__ A,
                   const float* __restrict__ pi,
                   float*       __restrict__ out) {
    extern __shared__ float smem[];
    float4* sA      = reinterpret_cast<float4*>(smem);        // [8][S_PITCH]
    float*  s_alpha = smem + 8 * S_PITCH * 4;                 // 4096 floats

    const int tid  = threadIdx.x;
    const int cta  = blockIdx.x;
    const int lane = tid & 31;            // row slot
    const int cg   = tid >> 5;            // warp id = column group, 0..7
    const int gcg  = cta * 8 + cg;
    const int col0 = cta * COLS_PER_CTA;

    const ulonglong2* __restrict__ A4u =
        reinterpret_cast<const ulonglong2*>(A);
    const float4* __restrict__ A4base =
        reinterpret_cast<const float4*>(A) + cta * 8;

    // ---- prologue: tier-1 rows in registers ----
    ulonglong2 rA[KR];
    #pragma unroll
    for (int k = 0; k < KR; ++k)
        rA[k] = A4u[(size_t)(lane + 32 * k) * 1024 + gcg];

    // ---- prologue: tier-2 rows into SMEM, [cg][row] layout ----
    for (int idx = tid; idx < S_ROWS * 8; idx += NTHR) {
        int cgf = idx & 7, rr = idx >> 3;
        sA[cgf * S_PITCH + rr] = A4base[(size_t)(R_ROWS + rr) * 1024 + cgf];
    }

    const ulonglong2* __restrict__ sAw =
        reinterpret_cast<const ulonglong2*>(sA + cg * S_PITCH);
    const ulonglong2* __restrict__ A3w =
        reinterpret_cast<const ulonglong2*>(g_A3T) + (size_t)gcg * T3_ROWS;

    unsigned local_sense = 0;

    // ---- alpha0 = pi * Bo[0] ----
    if (tid < COLS_PER_CTA) {
        int j = col0 + tid;
        g_alpha[0][j] = pi[j] * g_Bo[j];
    }
    grid_barrier(local_sense, cta);                // barrier #1

    int cur = 0;
    for (int t = 1; t < SEQ_T; ++t) {
        float4 bo;
        if (lane == 0)
            bo = reinterpret_cast<const float4*>(g_Bo + t * N_STATES)[gcg];

        // stage alpha into smem (1024 float4 = 4 per thread)
        {
            const float4* asrc = reinterpret_cast<const float4*>(g_alpha[cur]);
            float4*       adst = reinterpret_cast<float4*>(s_alpha);
            #pragma unroll
            for (int k = 0; k < 4; ++k)
                adst[tid + k * NTHR] = asrc[tid + k * NTHR];
        }
        __syncthreads();

        // dot partials: i = lane + 32k, k ascending 0..127 (order contract)
        unsigned long long acc01 = 0ull, acc23 = 0ull;

        #pragma unroll
        for (int k = 0; k < KR; ++k) {                   // tier 1: registers
            unsigned long long aa = pack2(s_alpha[lane + 32 * k]);
            fma2(acc01, rA[k].x, aa);
            fma2(acc23, rA[k].y, aa);
        }
        #pragma unroll 8
        for (int k = 0; k < KS; ++k) {                   // tier 2: SMEM
            unsigned long long aa = pack2(s_alpha[R_ROWS + lane + 32 * k]);
            ulonglong2 v = sAw[lane + 32 * k];
            fma2(acc01, v.x, aa);
            fma2(acc23, v.y, aa);
        }
        #pragma unroll 8
        for (int k = 0; k < KT; ++k) {                   // tier 3: L2 (transposed)
            unsigned long long aa = pack2(s_alpha[T3_OFF + lane + 32 * k]);
            ulonglong2 v = A3w[lane + 32 * k];
            fma2(acc01, v.x, aa);
            fma2(acc23, v.y, aa);
        }

        // unpack + xor butterfly (== R1's 32-slot tree at lane 0)
        float4 r;
        asm("mov.b64 {%0, %1}, %2;" : "=f"(r.x), "=f"(r.y) : "l"(acc01));
        asm("mov.b64 {%0, %1}, %2;" : "=f"(r.z), "=f"(r.w) : "l"(acc23));
        #pragma unroll
        for (int m = 16; m > 0; m >>= 1) {
            r.x += __shfl_xor_sync(0xffffffffu, r.x, m);
            r.y += __shfl_xor_sync(0xffffffffu, r.y, m);
            r.z += __shfl_xor_sync(0xffffffffu, r.z, m);
            r.w += __shfl_xor_sync(0xffffffffu, r.w, m);
        }

        if (lane == 0) {
            float4 o4;
            o4.x = r.x * bo.x; o4.y = r.y * bo.y;
            o4.z = r.z * bo.z; o4.w = r.w * bo.w;
            reinterpret_cast<float4*>(g_alpha[cur ^ 1])[gcg] = o4;
        }

        grid_barrier(local_sense, cta);            // barriers #2..#1024 (even)
        cur ^= 1;
    }

    // ---- final sum (CTA 0, 256 threads — identical to R1/R5) ----
    if (cta == 0) {
        float s = 0.f;
        for (int i = tid; i < N_STATES; i += NTHR)
            s += g_alpha[cur][i];
        s_alpha[tid] = s;
        __syncthreads();
        #pragma unroll
        for (int k = NTHR / 2; k > 0; k >>= 1) {
            if (tid < k) s_alpha[tid] += s_alpha[tid + k];
            __syncthreads();
        }
        if (tid == 0) out[0] = s_alpha[0];
    }
}

// ---------------------------------------------------------------------------
extern "C" void kernel_launch(void* const* d_in, const int* in_sizes, int n_in,
                              void* d_out, int out_size) {
    const float* A   = (const float*)d_in[0];
    const float* B   = (const float*)d_in[1];
    const float* pi  = (const float*)d_in[2];
    const int*   obs = (const int*)d_in[3];
    float* out = (float*)d_out;

    cudaFuncSetAttribute(hmm_forward_kernel,
                         cudaFuncAttributeMaxDynamicSharedMemorySize, SMEM_BYTES);

    gather_Bo_kernel<<<SEQ_T, 256>>>(B, obs);
    dim3 tgrid(T3_ROWS / 32, 1024 / 32);
    transpose_A3_kernel<<<tgrid, 256>>>(A);
    hmm_forward_kernel<<<NCTA, NTHR, SMEM_BYTES>>>(A, pi, out);
}

// round 8
// speedup vs baseline: 1.0651x; 1.0651x over previous
#include <cuda_runtime.h>

// HMM forward: alpha_{t+1} = (alpha_t @ A) * Bo[t],  answer = sum(alpha_{T-1})
//
// R8: 512 threads = 16 warps per CTA; warp w owns column PAIR (2 cols).
// Per (row-slot, col) the FMA chain is still i = lane + 32k, k ascending
// 0..127 and the 32-lane xor butterfly is the same tree -> per-step alpha
// bit-identical to R5 (measured rel_err 9.477166e-4). Doubling warps/SMSP
// (2 -> 4) attacks the measured stall-boundedness (issue ~13%, regs 255):
// per-thread pinning halves, regs ~115 < 128 cap, pipelining headroom.
// Barrier: R5's single-counter (R7 proved fan-in is SLOWER: arrivals
// pipeline at ~0.85cyc in LTS; fan-in added serial L2 round trips).
//
// Tiers per column: rows [0,1152) RF (36 x ull), rows [1152,2784) SMEM
// (51 k-slots, 209KB), rows [2784,4096) L2 via pair-major g_A3T (41 slots).

#define N_STATES 4096
#define SEQ_T    1024
#define N_OBS    128
#define NCTA     128
#define NTHR     512
#define NPAIR    16                  // column pairs per CTA

#define KR 36
#define KS 51
#define KT 41                        // 36+51+41 = 128
#define R_ROWS (KR * 32)             // 1152
#define S_ROWS (KS * 32)             // 1632
#define T3_OFF (R_ROWS + S_ROWS)     // 2784
#define T3_ROWS (KT * 32)            // 1312
#define S_PITCH (S_ROWS + 2)         // 1634 (8B elems)

// dynamic smem: sAp[16][S_PITCH] ull (209,152B) + s_alpha[4096] f32 = 225,536B
#define SMEM_BYTES (NPAIR * S_PITCH * 8 + N_STATES * 4)

typedef unsigned long long ull;

__device__ float    g_Bo[SEQ_T * N_STATES];
__device__ ull      g_A3T[2048 * T3_ROWS];     // [pair][row - T3_OFF]
__device__ float    g_alpha[2][N_STATES];
__device__ unsigned g_count;
__device__ unsigned g_sense;   // even #flips per launch -> restored

// ---------------------------------------------------------------------------
__global__ void gather_Bo_kernel(const float* __restrict__ B,
                                 const int*   __restrict__ obs_raw) {
    int any = 0;
    for (int k = 1 + 2 * (int)threadIdx.x; k < 1024; k += 2 * (int)blockDim.x)
        any |= obs_raw[k];
    int is32 = __syncthreads_or(any);

    int t = blockIdx.x;
    int o = is32 ? obs_raw[t] : obs_raw[2 * t];

    for (int j = threadIdx.x; j < N_STATES; j += blockDim.x)
        g_Bo[t * N_STATES + j] = B[j * N_OBS + o];
}

// ---------------------------------------------------------------------------
// Transpose rows [T3_OFF,4096) of A into pair-major g_A3T[pair][row].
__global__ void transpose_A3_kernel(const float* __restrict__ A) {
    __shared__ ull tile[32][33];
    const ull* A8 = reinterpret_cast<const ull*>(A);
    int r0 = blockIdx.x * 32;            // 41 tiles over 1312 rows
    int c0 = blockIdx.y * 32;            // 64 tiles over 2048 pairs
    int tx = threadIdx.x & 31, ty = threadIdx.x >> 5;
    #pragma unroll
    for (int p = 0; p < 4; ++p) {
        int r = r0 + ty + 8 * p;
        tile[ty + 8 * p][tx] = A8[(size_t)(T3_OFF + r) * 2048 + (c0 + tx)];
    }
    __syncthreads();
    #pragma unroll
    for (int p = 0; p < 4; ++p) {
        int c = c0 + ty + 8 * p;
        g_A3T[(size_t)c * T3_ROWS + (r0 + tx)] = tile[tx][ty + 8 * p];
    }
}

// ---------------------------------------------------------------------------
// Single-counter sense-reversing grid barrier (R5-proven).
__device__ __forceinline__ void grid_barrier(unsigned& local_sense, unsigned nblocks) {
    __syncthreads();
    if (threadIdx.x == 0) {
        unsigned s = local_sense ^ 1u;
        local_sense = s;
        __threadfence();
        if (atomicAdd(&g_count, 1u) == nblocks - 1u) {
            g_count = 0u;
            __threadfence();
            atomicExch(&g_sense, s);
        } else {
            while (*(volatile unsigned*)&g_sense != s) { }
        }
        __threadfence();
    }
    __syncthreads();
}

// packed f32x2 fma: component-wise IEEE fp32 fma (bit-identical to scalar)
__device__ __forceinline__ void fma2(ull& d, ull v, ull a) {
    asm("fma.rn.f32x2 %0, %1, %2, %0;" : "+l"(d) : "l"(v), "l"(a));
}
__device__ __forceinline__ ull pack2(float a) {
    ull r;
    asm("mov.b64 %0, {%1, %2};" : "=l"(r) : "f"(a), "f"(a));
    return r;
}

// ---------------------------------------------------------------------------
__global__ void __launch_bounds__(NTHR, 1)
hmm_forward_kernel(const float* __restrict__ A,
                   const float* __restrict__ pi,
                   float*       __restrict__ out) {
    extern __shared__ float smem[];
    ull*   sAp     = reinterpret_cast<ull*>(smem);             // [16][S_PITCH]
    float* s_alpha = smem + NPAIR * S_PITCH * 2;               // 4096 floats

    const int tid   = threadIdx.x;
    const int cta   = blockIdx.x;
    const int lane  = tid & 31;           // row slot
    const int wid   = tid >> 5;           // warp id = local column pair, 0..15
    const int gpair = cta * NPAIR + wid;  // global column pair (0..2047)
    const int col0  = cta * 32;

    const ull* __restrict__ A8 = reinterpret_cast<const ull*>(A);

    // ---- prologue: tier-1 rows in registers (one ull = this warp's pair) ----
    ull rA[KR];
    #pragma unroll
    for (int k = 0; k < KR; ++k)
        rA[k] = A8[(size_t)(lane + 32 * k) * 2048 + gpair];

    // ---- prologue: tier-2 rows into SMEM, [pair][row] layout ----
    for (int idx = tid; idx < S_ROWS * NPAIR; idx += NTHR) {
        int pr = idx & (NPAIR - 1), rr = idx >> 4;
        sAp[pr * S_PITCH + rr] =
            A8[(size_t)(R_ROWS + rr) * 2048 + cta * NPAIR + pr];
    }

    const ull* __restrict__ sAw = sAp + wid * S_PITCH;
    const ull* __restrict__ A3w = g_A3T + (size_t)gpair * T3_ROWS;

    unsigned local_sense = 0;

    // ---- alpha0 = pi * Bo[0] ----
    if (tid < 32) {
        int j = col0 + tid;
        g_alpha[0][j] = pi[j] * g_Bo[j];
    }
    grid_barrier(local_sense, gridDim.x);          // barrier #1

    int cur = 0;
    for (int t = 1; t < SEQ_T; ++t) {
        float2 bo;
        if (lane == 0)
            bo = reinterpret_cast<const float2*>(g_Bo + t * N_STATES)[gpair];

        // stage alpha into smem (1024 float4 = 2 per thread)
        {
            const float4* asrc = reinterpret_cast<const float4*>(g_alpha[cur]);
            float4*       adst = reinterpret_cast<float4*>(s_alpha);
            adst[tid]        = asrc[tid];
            adst[tid + NTHR] = asrc[tid + NTHR];
        }
        __syncthreads();

        // dot partials: i = lane + 32k, k ascending 0..127 (order contract)
        ull acc = 0ull;

        #pragma unroll
        for (int k = 0; k < KR; ++k)                     // tier 1: registers
            fma2(acc, rA[k], pack2(s_alpha[lane + 32 * k]));
        #pragma unroll 8
        for (int k = 0; k < KS; ++k)                     // tier 2: SMEM
            fma2(acc, sAw[lane + 32 * k],
                 pack2(s_alpha[R_ROWS + lane + 32 * k]));
        #pragma unroll 8
        for (int k = 0; k < KT; ++k)                     // tier 3: L2 (pair-major)
            fma2(acc, A3w[lane + 32 * k],
                 pack2(s_alpha[T3_OFF + lane + 32 * k]));

        // unpack + xor butterfly (same per-column tree as R1/R5)
        float2 r;
        asm("mov.b64 {%0, %1}, %2;" : "=f"(r.x), "=f"(r.y) : "l"(acc));
        #pragma unroll
        for (int m = 16; m > 0; m >>= 1) {
            r.x += __shfl_xor_sync(0xffffffffu, r.x, m);
            r.y += __shfl_xor_sync(0xffffffffu, r.y, m);
        }

        if (lane == 0) {
            float2 o2;
            o2.x = r.x * bo.x;
            o2.y = r.y * bo.y;
            reinterpret_cast<float2*>(g_alpha[cur ^ 1])[gpair] = o2;
        }

        grid_barrier(local_sense, gridDim.x);      // barriers #2..#1024 (even)
        cur ^= 1;
    }

    // ---- final sum (CTA 0): R1's exact 256-thread tree ----
    if (cta == 0) {
        if (tid < 256) {
            float s = 0.f;
            for (int i = tid; i < N_STATES; i += 256)
                s += g_alpha[cur][i];
            s_alpha[tid] = s;
        }
        __syncthreads();
        #pragma unroll
        for (int k = 128; k > 0; k >>= 1) {
            if (tid < k) s_alpha[tid] += s_alpha[tid + k];
            __syncthreads();
        }
        if (tid == 0) out[0] = s_alpha[0];
    }
}

// ---------------------------------------------------------------------------
extern "C" void kernel_launch(void* const* d_in, const int* in_sizes, int n_in,
                              void* d_out, int out_size) {
    const float* A   = (const float*)d_in[0];
    const float* B   = (const float*)d_in[1];
    const float* pi  = (const float*)d_in[2];
    const int*   obs = (const int*)d_in[3];
    float* out = (float*)d_out;

    cudaFuncSetAttribute(hmm_forward_kernel,
                         cudaFuncAttributeMaxDynamicSharedMemorySize, SMEM_BYTES);

    gather_Bo_kernel<<<SEQ_T, 256>>>(B, obs);
    dim3 tgrid(T3_ROWS / 32, 2048 / 32);
    transpose_A3_kernel<<<tgrid, 256>>>(A);
    hmm_forward_kernel<<<NCTA, NTHR, SMEM_BYTES>>>(A, pi, out);
}